// round 5
// baseline (speedup 1.0000x reference)
#include <cuda_runtime.h>
#include <cstdint>

// 64 steps of diffusion-advection on a 1024x1024 periodic grid, emitting
// (T, 3, H, W) fp32 RGB, as ONE persistent kernel.
//
// Key facts:
//  - r channel of frame s == u_{s+1} exactly (both clipped to [0,1]), so the
//    frames array itself carries the evolving state; no scratch buffer.
//  - Frame memory is write-once, so cross-block sync needs only monotonic
//    per-block progress flags (release: fence+flag store; acquire: spin+fence).
//  - Each block owns 2 full rows; u lives in registers (2 float4/thread).
//    Per step it reads 2 halo rows (neighbors' r-channel writes, L2 hits)
//    and 4 warp-edge scalars, computes, stores rgb.

#define HH 1024
#define WW 1024
#define HW (HH * WW)

#define DT     0.1f
#define ALPHA  0.05f
#define V_X    0.1f
// V_Y == 0 -> du_dy term vanishes.

#define NB 512              // blocks; 2 rows per block
#define FLAG_STRIDE 32      // ints -> 128 B per flag, no false sharing

__device__ volatile int g_progress[NB * FLAG_STRIDE];

__global__ void reset_flags_kernel() {
    g_progress[threadIdx.x * FLAG_STRIDE] = 0;
}

__global__ __launch_bounds__(256, 4)
void physics_persistent_kernel(const float* __restrict__ u_init,
                               float* __restrict__ frames,
                               int n_frames)
{
    const int b    = blockIdx.x;
    const int c4   = threadIdx.x;        // float4 column 0..255
    const int lane = c4 & 31;
    const int y0   = b * 2;              // owned rows y0, y0+1
    const int yum1 = (y0 - 1) & (HH - 1);
    const int yp2  = (y0 + 2) & (HH - 1);
    const int bup  = (b - 1) & (NB - 1);
    const int bdn  = (b + 1) & (NB - 1);
    const int x0   = c4 << 2;
    const int xm1  = (x0 - 1) & (WW - 1);
    const int xp4  = (x0 + 4) & (WW - 1);

    const float4* in4 = (const float4*)u_init;
    float4 u0 = in4[y0 * 256 + c4];
    float4 u1 = in4[y0 * 256 + 256 + c4];

    for (int s = 0; s < n_frames; ++s) {
        // u_s lives in: input (s=0) or r channel of frame s-1.
        const float* usrc = (s == 0) ? u_init
                                     : (frames + (size_t)(s - 1) * 3 * HW);
        const float4* usrc4 = (const float4*)usrc;

        // Acquire: neighbors must have published u_s (their frame s-1 rows).
        if (s > 0) {
            if (c4 == 0) {
                while (g_progress[bup * FLAG_STRIDE] < s) { }
                while (g_progress[bdn * FLAG_STRIDE] < s) { }
                __threadfence();
            }
            __syncthreads();
        }

        // Halo rows (same column, neighbors' data).
        const float4 hu = __ldcg(&usrc4[yum1 * 256 + c4]);
        const float4 hd = __ldcg(&usrc4[yp2 * 256 + c4]);

        // Warp-edge x-neighbors (own block's data from u_s).
        float e0l = 0.f, e0r = 0.f, e1l = 0.f, e1r = 0.f;
        if (lane == 0) {
            e0l = __ldcg(&usrc[y0 * WW + xm1]);
            e1l = __ldcg(&usrc[y0 * WW + WW + xm1]);
        }
        if (lane == 31) {
            e0r = __ldcg(&usrc[y0 * WW + xp4]);
            e1r = __ldcg(&usrc[y0 * WW + WW + xp4]);
        }

        float l0 = __shfl_up_sync(0xffffffffu, u0.w, 1);
        float r0 = __shfl_down_sync(0xffffffffu, u0.x, 1);
        float l1 = __shfl_up_sync(0xffffffffu, u1.w, 1);
        float r1 = __shfl_down_sync(0xffffffffu, u1.x, 1);
        if (lane == 0)  { l0 = e0l; l1 = e1l; }
        if (lane == 31) { r0 = e0r; r1 = e1r; }

        // Row y0: up = hu, down = u1.  Row y0+1: up = u0, down = hd.
        const float uc0[4] = {u0.x, u0.y, u0.z, u0.w};
        const float ul0[4] = {l0,   u0.x, u0.y, u0.z};
        const float ur0[4] = {u0.y, u0.z, u0.w, r0};
        const float uu0[4] = {hu.x, hu.y, hu.z, hu.w};
        const float ud0[4] = {u1.x, u1.y, u1.z, u1.w};

        const float uc1[4] = {u1.x, u1.y, u1.z, u1.w};
        const float ul1[4] = {l1,   u1.x, u1.y, u1.z};
        const float ur1[4] = {u1.y, u1.z, u1.w, r1};
        const float uu1[4] = {u0.x, u0.y, u0.z, u0.w};
        const float ud1[4] = {hd.x, hd.y, hd.z, hd.w};

        float4 n0, n1, g0, g1, bb0, bb1;
        float* n0p = &n0.x; float* n1p = &n1.x;
        float* g0p = &g0.x; float* g1p = &g1.x;
        float* b0p = &bb0.x; float* b1p = &bb1.x;

        #pragma unroll
        for (int i = 0; i < 4; ++i) {
            float lap = ul0[i] + ur0[i] + uu0[i] + ud0[i] - 4.0f * uc0[i];
            float v = uc0[i] + DT * (ALPHA * lap - V_X * (uc0[i] - ul0[i]));
            v = fminf(fmaxf(v, 0.0f), 1.0f);
            n0p[i] = v; g0p[i] = v * 0.5f; b0p[i] = 1.0f - v;

            lap = ul1[i] + ur1[i] + uu1[i] + ud1[i] - 4.0f * uc1[i];
            v = uc1[i] + DT * (ALPHA * lap - V_X * (uc1[i] - ul1[i]));
            v = fminf(fmaxf(v, 0.0f), 1.0f);
            n1p[i] = v; g1p[i] = v * 0.5f; b1p[i] = 1.0f - v;
        }

        float4* f4 = (float4*)(frames + (size_t)s * 3 * HW);
        const int idx0 = y0 * 256 + c4;
        const int idx1 = idx0 + 256;

        // r channel: re-read next step (halos/edges) -> normal stores.
        f4[idx0] = n0;
        f4[idx1] = n1;
        // g, b: never re-read -> streaming stores.
        __stcs(&f4[idx0 + (HW / 4)], g0);
        __stcs(&f4[idx1 + (HW / 4)], g1);
        __stcs(&f4[idx0 + 2 * (HW / 4)], bb0);
        __stcs(&f4[idx1 + 2 * (HW / 4)], bb1);

        // Release: all threads' r stores -> fence -> barrier -> flag.
        __threadfence();
        __syncthreads();
        if (c4 == 0) g_progress[b * FLAG_STRIDE] = s + 1;

        u0 = n0;
        u1 = n1;
    }
}

extern "C" void kernel_launch(void* const* d_in, const int* in_sizes, int n_in,
                              void* d_out, int out_size) {
    const float* init = (const float*)d_in[0];
    float* out = (float*)d_out;
    const int n_frames = out_size / (3 * HW);

    reset_flags_kernel<<<1, NB>>>();
    physics_persistent_kernel<<<NB, 256>>>(init, out, n_frames);
}

// round 6
// speedup vs baseline: 1.2349x; 1.2349x over previous
#include <cuda_runtime.h>
#include <cstdint>

// 64 steps of diffusion-advection on a 1024x1024 periodic grid, emitting
// (T, 3, H, W) fp32 RGB, as ONE persistent kernel.
//
//  - r channel of frame s == u_{s+1} exactly (both clipped to [0,1]); the
//    frames array itself carries the state.
//  - Per-row progress flags; producer publishes with st.release.gpu after a
//    block barrier (cumulative), consumer spins with ld.acquire.gpu. No
//    membars, one __syncthreads per step.
//  - 1024 blocks x 256 threads, one row per block, u in registers.
//    __launch_bounds__(256,8) caps regs at 32 -> 1184 resident slots >= 1024
//    blocks: full co-residency guaranteed (spin-safe).

#define HH 1024
#define WW 1024
#define HW (HH * WW)

#define DT     0.1f
#define ALPHA  0.05f
#define V_X    0.1f
// V_Y == 0 -> du_dy term vanishes.

#define NB 1024
#define FS 32                 // flag stride in ints (128 B)

__device__ int g_flags[NB * FS];

__global__ void reset_flags_kernel() {
    const int i = blockIdx.x * blockDim.x + threadIdx.x;   // 0..NB-1
    g_flags[i * FS] = 0;
}

__device__ __forceinline__ int ld_acq(const int* p) {
    int v;
    asm volatile("ld.acquire.gpu.global.b32 %0, [%1];"
                 : "=r"(v) : "l"(p) : "memory");
    return v;
}
__device__ __forceinline__ void st_rel(int* p, int v) {
    asm volatile("st.release.gpu.global.b32 [%0], %1;"
                 :: "l"(p), "r"(v) : "memory");
}

__global__ __launch_bounds__(256, 8)
void physics_persistent_kernel(const float* __restrict__ u_init,
                               float* __restrict__ frames,
                               int n_frames)
{
    const int y    = blockIdx.x;          // owned row
    const int c4   = threadIdx.x;         // float4 column 0..255
    const int lane = c4 & 31;
    const int ym1  = (y - 1) & (HH - 1);
    const int yp1  = (y + 1) & (HH - 1);
    const int x0   = c4 << 2;

    const int idx  = (y   << 8) + c4;     // float4 index in a channel
    const int idxu = (ym1 << 8) + c4;
    const int idxd = (yp1 << 8) + c4;
    const int eL   = (y << 10) + ((x0 - 1) & (WW - 1));
    const int eR   = (y << 10) + ((x0 + 4) & (WW - 1));

    int*       flag_self = &g_flags[y   * FS];
    const int* flag_up   = &g_flags[ym1 * FS];
    const int* flag_dn   = &g_flags[yp1 * FS];

    float4 u = ((const float4*)u_init)[idx];   // u_s for own row
    const float* src = u_init;                 // where u_s lives
    float*       fr  = frames;                 // frame s base

    for (int s = 0; s < n_frames; ++s) {
        if (s > 0) {
            // neighbors must have published frame s-1 (their u_s)
            while (ld_acq(flag_up) < s) { }
            while (ld_acq(flag_dn) < s) { }
        }

        const float4* src4 = (const float4*)src;
        const float4 hu = __ldcg(&src4[idxu]);
        const float4 hd = __ldcg(&src4[idxd]);

        float lw = __shfl_up_sync(0xffffffffu, u.w, 1);
        float rx = __shfl_down_sync(0xffffffffu, u.x, 1);
        if (lane == 0)  lw = __ldcg(&src[eL]);
        if (lane == 31) rx = __ldcg(&src[eR]);

        const float uc[4] = {u.x,  u.y,  u.z,  u.w};
        const float ul[4] = {lw,   u.x,  u.y,  u.z};
        const float ur[4] = {u.y,  u.z,  u.w,  rx};
        const float uu[4] = {hu.x, hu.y, hu.z, hu.w};
        const float ud[4] = {hd.x, hd.y, hd.z, hd.w};

        float4 n;
        float* np = &n.x;
        #pragma unroll
        for (int i = 0; i < 4; ++i) {
            const float lap = ul[i] + ur[i] + uu[i] + ud[i] - 4.0f * uc[i];
            float v = uc[i] + DT * (ALPHA * lap - V_X * (uc[i] - ul[i]));
            np[i] = fminf(fmaxf(v, 0.0f), 1.0f);
        }

        float4* f4 = (float4*)fr;
        f4[idx] = n;                                   // r (re-read next step)

        float4 t;                                      // g, then b (reuse temp)
        t.x = n.x * 0.5f; t.y = n.y * 0.5f;
        t.z = n.z * 0.5f; t.w = n.w * 0.5f;
        __stcs(&f4[idx + (HW / 4)], t);
        t.x = 1.0f - n.x; t.y = 1.0f - n.y;
        t.z = 1.0f - n.z; t.w = 1.0f - n.w;
        __stcs(&f4[idx + 2 * (HW / 4)], t);

        // Publish: barrier (all threads' stores observed) -> release store.
        __syncthreads();
        if (c4 == 0) st_rel(flag_self, s + 1);

        u   = n;
        src = fr;          // r channel of frame s == u_{s+1}
        fr += 3 * HW;
    }
}

extern "C" void kernel_launch(void* const* d_in, const int* in_sizes, int n_in,
                              void* d_out, int out_size) {
    const float* init = (const float*)d_in[0];
    float* out = (float*)d_out;
    const int n_frames = out_size / (3 * HW);

    reset_flags_kernel<<<NB / 256, 256>>>();
    physics_persistent_kernel<<<NB, 256>>>(init, out, n_frames);
}

// round 7
// speedup vs baseline: 1.4092x; 1.1412x over previous
#include <cuda_runtime.h>
#include <cstdint>

// 64 steps of diffusion-advection on a 1024x1024 periodic grid, emitting
// (T, 3, H, W) fp32 RGB, as ONE persistent kernel.
//
//  - r channel of frame s == u_{s+1} exactly (clipped); frames carry state.
//  - Per-row flags: producer block-bar + st.release.gpu; consumer
//    ld.acquire.gpu spin. One __syncthreads per step.
//  - Critical-path trim: only the r store precedes the flag; g/b stores
//    (2/3 of traffic, never read) drain after publish, overlapping the next
//    step's spin + halo loads.
//  - Warp-edge x-neighbors exchanged through parity-double-buffered smem
//    (no global edge loads on the chain).

#define HH 1024
#define WW 1024
#define HW (HH * WW)

#define DT     0.1f
#define ALPHA  0.05f
#define V_X    0.1f
// V_Y == 0 -> du_dy term vanishes.

#define NB 1024
#define FS 32                 // flag stride in ints (128 B)

__device__ int g_flags[NB * FS];

__global__ void reset_flags_kernel() {
    const int i = blockIdx.x * blockDim.x + threadIdx.x;   // 0..NB-1
    g_flags[i * FS] = 0;
}

__device__ __forceinline__ int ld_acq(const int* p) {
    int v;
    asm volatile("ld.acquire.gpu.global.b32 %0, [%1];"
                 : "=r"(v) : "l"(p) : "memory");
    return v;
}
__device__ __forceinline__ void st_rel(int* p, int v) {
    asm volatile("st.release.gpu.global.b32 [%0], %1;"
                 :: "l"(p), "r"(v) : "memory");
}

__global__ __launch_bounds__(256, 8)
void physics_persistent_kernel(const float* __restrict__ u_init,
                               float* __restrict__ frames,
                               int n_frames)
{
    // Edge exchange: [parity][0=first elem of warp][wid], [parity][1=last][wid]
    __shared__ float sEdge[2][2][8];

    const int y    = blockIdx.x;          // owned row
    const int c4   = threadIdx.x;         // float4 column 0..255
    const int lane = c4 & 31;
    const int wid  = c4 >> 5;             // warp 0..7
    const int ym1  = (y - 1) & (HH - 1);
    const int yp1  = (y + 1) & (HH - 1);

    const int idx  = (y   << 8) + c4;     // float4 index within a channel
    const int idxu = (ym1 << 8) + c4;
    const int idxd = (yp1 << 8) + c4;

    int*       flag_self = &g_flags[y   * FS];
    const int* flag_up   = &g_flags[ym1 * FS];
    const int* flag_dn   = &g_flags[yp1 * FS];

    float4 u = ((const float4*)u_init)[idx];   // u_s for own row
    const float* src = u_init;                 // where u_s lives (r of s-1)
    float*       fr  = frames;                 // frame s base

    // Seed edge buffer (parity 0) with u_0 edges.
    if (lane == 0)  sEdge[0][0][wid] = u.x;
    if (lane == 31) sEdge[0][1][wid] = u.w;
    __syncthreads();

    for (int s = 0; s < n_frames; ++s) {
        if (s > 0) {
            while (ld_acq(flag_up) < s) { }
            while (ld_acq(flag_dn) < s) { }
        }

        const float4* src4 = (const float4*)src;
        const float4 hu = __ldcg(&src4[idxu]);
        const float4 hd = __ldcg(&src4[idxd]);

        const int par = s & 1;
        const float lwS = sEdge[par][1][(wid - 1) & 7];  // left warp's last
        const float rxS = sEdge[par][0][(wid + 1) & 7];  // right warp's first

        float lw = __shfl_up_sync(0xffffffffu, u.w, 1);
        float rx = __shfl_down_sync(0xffffffffu, u.x, 1);
        if (lane == 0)  lw = lwS;
        if (lane == 31) rx = rxS;

        const float uc[4] = {u.x,  u.y,  u.z,  u.w};
        const float ul[4] = {lw,   u.x,  u.y,  u.z};
        const float ur[4] = {u.y,  u.z,  u.w,  rx};
        const float uu[4] = {hu.x, hu.y, hu.z, hu.w};
        const float ud[4] = {hd.x, hd.y, hd.z, hd.w};

        float4 n;
        float* np = &n.x;
        #pragma unroll
        for (int i = 0; i < 4; ++i) {
            const float lap = ul[i] + ur[i] + uu[i] + ud[i] - 4.0f * uc[i];
            float v = uc[i] + DT * (ALPHA * lap - V_X * (uc[i] - ul[i]));
            np[i] = fminf(fmaxf(v, 0.0f), 1.0f);
        }

        float4* f4 = (float4*)fr;
        f4[idx] = n;                       // r channel: the only re-read data

        // Stage next step's edges (other parity slot; race-free).
        if (lane == 0)  sEdge[par ^ 1][0][wid] = n.x;
        if (lane == 31) sEdge[par ^ 1][1][wid] = n.w;

        // Publish: barrier (all r stores + edge STS ordered) -> release.
        __syncthreads();
        if (c4 == 0) st_rel(flag_self, s + 1);

        // g/b: never read by anyone -> off the critical chain, streaming.
        float4 t;
        t.x = n.x * 0.5f; t.y = n.y * 0.5f;
        t.z = n.z * 0.5f; t.w = n.w * 0.5f;
        __stcs(&f4[idx + (HW / 4)], t);
        t.x = 1.0f - n.x; t.y = 1.0f - n.y;
        t.z = 1.0f - n.z; t.w = 1.0f - n.w;
        __stcs(&f4[idx + 2 * (HW / 4)], t);

        u   = n;
        src = fr;          // r channel of frame s == u_{s+1}
        fr += 3 * HW;
    }
}

extern "C" void kernel_launch(void* const* d_in, const int* in_sizes, int n_in,
                              void* d_out, int out_size) {
    const float* init = (const float*)d_in[0];
    float* out = (float*)d_out;
    const int n_frames = out_size / (3 * HW);

    reset_flags_kernel<<<NB / 256, 256>>>();
    physics_persistent_kernel<<<NB, 256>>>(init, out, n_frames);
}